// round 1
// baseline (speedup 1.0000x reference)
#include <cuda_runtime.h>

#define NS     8
#define NC     128
#define KT     32
#define KF     16
#define LPOST  400
#define LPRE   431
#define FREQ   256
#define NFW    15
#define THR    15.0f

// pool[s][c][fwin], binary
__device__ int g_pool[NS * NC * NFW];

#define TILE_COLS   33                    // 31 valid cols + pad -> conflict-free lane->t LDS
#define TILE_PAD    14224                 // 431*33 = 14223, padded to 16B-aligned float offset
#define WARPS       16
#define WST_PER_WARP 2048                 // 4 channels * 512 weights, interleaved

__global__ __launch_bounds__(512, 1)
void conv_pool_kernel(const float* __restrict__ X, const float* __restrict__ W)
{
    extern __shared__ float sm[];
    float* tile = sm;                      // [431][33]
    float* wst  = sm + TILE_PAD;           // 16 warps * 2048 floats

    const int s    = blockIdx.x / NFW;
    const int fwin = blockIdx.x % NFW;
    const int tid  = threadIdx.x;
    const int lane = tid & 31;
    const int wid  = tid >> 5;
    const int sec_start = s * 400;
    const int col0 = fwin * 16;

    // Stage X window: rows [sec_start, sec_start+431), cols [col0, col0+31)
    for (int i = tid; i < LPRE * 31; i += 512) {
        int r = i / 31, c = i - r * 31;
        tile[r * TILE_COLS + c] = X[(sec_start + r) * FREQ + col0 + c];
    }
    __syncthreads();

    float* wsm = wst + wid * WST_PER_WARP;
    const float* Wsec = W + s * (NC * KT * KF);

    // Each warp covers channels [wid*8, wid*8+8), two groups of 4.
    for (int g = 0; g < 2; ++g) {
        const int cbase = wid * 8 + g * 4;

        __syncwarp();
        // Interleave weights: wsm[kk*4 + j] = W[s][cbase+j][kk]  (kk = kt*16+kf)
        for (int i = lane; i < WST_PER_WARP; i += 32) {
            int j = i & 3, kk = i >> 2;
            wsm[i] = Wsec[(cbase + j) * (KT * KF) + kk];
        }
        __syncwarp();

        unsigned fired = 0u;
        for (int fof = 0; fof < 16 && fired != 0xFu; ++fof) {
            for (int t0 = 0; t0 < 400 && fired != 0xFu; t0 += 32) {
                int t = t0 + lane;
                if (t > 399) t = 399;               // duplicate pot(399): harmless for "any"
                const float*  xr = tile + t * TILE_COLS + fof;
                const float4* wr = (const float4*)wsm;
                float a0 = 0.f, a1 = 0.f, a2 = 0.f, a3 = 0.f;
                #pragma unroll 4
                for (int kt = 0; kt < KT; ++kt) {
                    #pragma unroll
                    for (int kf = 0; kf < KF; ++kf) {
                        float  x = xr[kf];          // conflict-free scalar LDS (33-col pad)
                        float4 w = wr[kf];          // warp-uniform LDS.128 broadcast
                        a0 = fmaf(x, w.x, a0);
                        a1 = fmaf(x, w.y, a1);
                        a2 = fmaf(x, w.z, a2);
                        a3 = fmaf(x, w.w, a3);
                    }
                    xr += TILE_COLS;
                    wr += 16;
                }
                if (__ballot_sync(0xffffffffu, a0 >= THR)) fired |= 1u;
                if (__ballot_sync(0xffffffffu, a1 >= THR)) fired |= 2u;
                if (__ballot_sync(0xffffffffu, a2 >= THR)) fired |= 4u;
                if (__ballot_sync(0xffffffffu, a3 >= THR)) fired |= 8u;
            }
        }
        if (lane < 4)
            g_pool[(s * NC + cbase + lane) * NFW + fwin] = (int)((fired >> lane) & 1u);
    }
}

// Winner logic:
//   cnt[c,f]   = sum_s pool
//   e          = clip(8 - cnt, 0, 7); values = pool[e]
//   v          = 8 * (exists cell with cnt>0 && values==1)
//   total[c,f] = cnt * (values + v)
//   out        = (max total != 0) ? (first flat argmax)/15 : -1
__global__ void reduce_kernel(int* __restrict__ out)
{
    __shared__ int s_any;
    __shared__ int s_key;
    __shared__ unsigned char scnt[NC * NFW];
    __shared__ unsigned char sval[NC * NFW];

    const int tid = threadIdx.x;
    if (tid == 0) { s_any = 0; s_key = -1; }
    __syncthreads();

    for (int cell = tid; cell < NC * NFW; cell += blockDim.x) {
        int cnt = 0;
        #pragma unroll
        for (int s = 0; s < NS; ++s) cnt += g_pool[s * (NC * NFW) + cell];
        int e = 8 - cnt;
        if (e < 0) e = 0;
        if (e > 7) e = 7;
        int val = g_pool[e * (NC * NFW) + cell];
        scnt[cell] = (unsigned char)cnt;
        sval[cell] = (unsigned char)val;
        if (cnt > 0 && val > 0) atomicOr(&s_any, 1);
    }
    __syncthreads();

    const int v = s_any * 8;
    for (int cell = tid; cell < NC * NFW; cell += blockDim.x) {
        int total = (int)scnt[cell] * ((int)sval[cell] + v);
        // maximize (total, -cell): first-occurrence argmax tie-break
        int key = (total << 11) | (2047 - cell);
        atomicMax(&s_key, key);
    }
    __syncthreads();

    if (tid == 0) {
        int key   = s_key;
        int total = key >> 11;
        int cell  = 2047 - (key & 2047);
        out[0] = (total != 0) ? (cell / NFW) : -1;
    }
}

extern "C" void kernel_launch(void* const* d_in, const int* in_sizes, int n_in,
                              void* d_out, int out_size)
{
    (void)n_in; (void)out_size;
    const float* X = (const float*)d_in[0];
    const float* W = (const float*)d_in[1];
    // Robustness: identify by element count (X = 3231*256 = 827136, W = 8*128*512 = 524288)
    if (in_sizes[0] == NS * NC * KT * KF) { const float* t = X; X = W; W = t; }

    const size_t smem = (size_t)(TILE_PAD + WARPS * WST_PER_WARP) * sizeof(float); // 187,968 B
    cudaFuncSetAttribute(conv_pool_kernel,
                         cudaFuncAttributeMaxDynamicSharedMemorySize, (int)smem);

    conv_pool_kernel<<<NS * NFW, 512, smem>>>(X, W);
    reduce_kernel<<<1, 256>>>((int*)d_out);
}

// round 2
// speedup vs baseline: 2.5353x; 2.5353x over previous
#include <cuda_runtime.h>

#define NS     8
#define NC     128
#define KT     32
#define KF     16
#define FREQ   256
#define NFW    15
#define THR    15.0f
#define LPRE   431

#define TCOLS       31
#define TILE_PAD    13364              // 431*31 = 13361, padded for alignment
#define WPITCH      65                 // 64 channels + 1 pad -> conflict-free transposed LDS/STS
#define WSM_FLOATS  (512 * WPITCH)     // 33280
#define SMEM_FLOATS (TILE_PAD + WSM_FLOATS)   // 46644 floats = 186,576 B

// pool bit per (section, fwin, channel)
__device__ int      g_pool[NS * NFW * NC];
__device__ unsigned g_done;            // zero at load; last CTA resets to 0 each run

__global__ __launch_bounds__(256, 1)
void conv_pool_winner_kernel(const float* __restrict__ X,
                             const float* __restrict__ W,
                             int* __restrict__ out)
{
    extern __shared__ float sm[];
    float* tile = sm;                  // [431][31] x window
    float* wsm  = sm + TILE_PAD;       // transposed weights [512][WPITCH]

    __shared__ unsigned s_fired[2];
    __shared__ int s_last, s_any, s_key;

    const int s    = blockIdx.x / NFW;
    const int fwin = blockIdx.x % NFW;
    const int tid  = threadIdx.x;
    const int lane = tid & 31;
    const int c    = tid & 63;         // channel within half
    const int j    = tid >> 6;         // probe slot 0..3 (uniform per warp)
    const int col0 = fwin * 16;
    const int sec  = s * 400;

    // ---- stage X window [sec..sec+431) x [col0..col0+31) ----
    for (int r = tid >> 5; r < LPRE; r += 8)
        if (lane < TCOLS)
            tile[r * TCOLS + lane] = X[(sec + r) * FREQ + col0 + lane];

    const float4* W4 = (const float4*)(W + (size_t)s * NC * KT * KF);

    for (int half = 0; half < 2; ++half) {
        const int cbase = half * 64;
        __syncthreads();                       // wsm reuse + fired reset barrier
        if (tid < 2) s_fired[tid] = 0u;

        // stage W transposed: wsm[kk*65 + cc] = W[s][cbase+cc][kk]
        for (int i = tid; i < 64 * 128; i += 256) {
            int cc = i >> 7, k4 = i & 127;
            float4 w = W4[(cbase + cc) * 128 + k4];
            int kk = k4 * 4;
            wsm[(kk + 0) * WPITCH + cc] = w.x;
            wsm[(kk + 1) * WPITCH + cc] = w.y;
            wsm[(kk + 2) * WPITCH + cc] = w.z;
            wsm[(kk + 3) * WPITCH + cc] = w.w;
        }
        __syncthreads();

        // ---- probe loop: full coverage of 6400 pots in decorrelated order ----
        for (int k = 0; k < 1600; ++k) {
            bool mine = ((s_fired[c >> 5] >> (c & 31)) & 1u) == 0u;
            if (__ballot_sync(0xffffffffu, mine)) {
                if (mine) {
                    int p   = k * 4 + j;              // 0..6399, each exactly once
                    int idx = (p * 2339) % 6400;      // gcd(2339,6400)=1
                    int t   = idx >> 4;               // 0..399
                    int f   = idx & 15;               // 0..15
                    const float* xr = tile + t * TCOLS + f;
                    const float* wr = wsm + c;
                    float a0 = 0.f, a1 = 0.f, a2 = 0.f, a3 = 0.f;
                    #pragma unroll 4
                    for (int kt = 0; kt < KT; ++kt) {
                        const float* xq = xr + kt * TCOLS;
                        const float* wq = wr + kt * KF * WPITCH;
                        #pragma unroll
                        for (int kf = 0; kf < KF; kf += 4) {
                            a0 = fmaf(xq[kf + 0], wq[(kf + 0) * WPITCH], a0);
                            a1 = fmaf(xq[kf + 1], wq[(kf + 1) * WPITCH], a1);
                            a2 = fmaf(xq[kf + 2], wq[(kf + 2) * WPITCH], a2);
                            a3 = fmaf(xq[kf + 3], wq[(kf + 3) * WPITCH], a3);
                        }
                    }
                    float pot = (a0 + a1) + (a2 + a3);
                    if (pot >= THR) atomicOr(&s_fired[c >> 5], 1u << (c & 31));
                }
            }
            __syncthreads();
            if ((s_fired[0] & s_fired[1]) == 0xffffffffu) break;
        }

        if (tid < 64)
            g_pool[(s * NFW + fwin) * NC + cbase + tid] =
                (int)((s_fired[tid >> 5] >> (tid & 31)) & 1u);
    }

    // ---- fused winner reduction: last CTA to finish does it ----
    __threadfence();
    if (tid == 0) {
        unsigned n = atomicAdd(&g_done, 1u);
        s_last = (n == gridDim.x - 1u);
    }
    __syncthreads();
    if (!s_last) return;
    __threadfence();

    unsigned char* mbuf = (unsigned char*)sm;   // reuse smem (post-sync)
    if (tid == 0) { s_any = 0; s_key = -1; }
    __syncthreads();

    int localany = 0;
    for (int cell = tid; cell < NC * NFW; cell += 256) {
        int cc = cell / NFW, f = cell % NFW;    // flat order c*15+f (matches jnp.argmax)
        unsigned mask = 0; int cnt = 0;
        #pragma unroll
        for (int ss = 0; ss < NS; ++ss) {
            int b = g_pool[(ss * NFW + f) * NC + cc];
            mask |= (unsigned)b << ss;
            cnt  += b;
        }
        int e = 8 - cnt; e = e < 0 ? 0 : (e > 7 ? 7 : e);
        int val = (int)((mask >> e) & 1u);
        mbuf[cell] = (unsigned char)((cnt << 1) | val);
        if (cnt > 0 && val > 0) localany = 1;
    }
    if (localany) atomicOr(&s_any, 1);
    __syncthreads();

    const int v = s_any * 8;
    for (int cell = tid; cell < NC * NFW; cell += 256) {
        int d = mbuf[cell];
        int total = (d >> 1) * ((d & 1) + v);
        int key = (total << 11) | (2047 - cell);   // first-occurrence argmax tie-break
        atomicMax(&s_key, key);
    }
    __syncthreads();

    if (tid == 0) {
        int key   = s_key;
        int total = key >> 11;
        int cell  = 2047 - (key & 2047);
        out[0] = total ? (cell / NFW) : -1;
        g_done = 0;                               // reset for next replay
    }
}

extern "C" void kernel_launch(void* const* d_in, const int* in_sizes, int n_in,
                              void* d_out, int out_size)
{
    (void)n_in; (void)out_size;
    const float* X = (const float*)d_in[0];
    const float* W = (const float*)d_in[1];
    if (in_sizes[0] == NS * NC * KT * KF) { const float* t = X; X = W; W = t; }

    const size_t smem = (size_t)SMEM_FLOATS * sizeof(float);   // 186,576 B
    cudaFuncSetAttribute(conv_pool_winner_kernel,
                         cudaFuncAttributeMaxDynamicSharedMemorySize, (int)smem);

    conv_pool_winner_kernel<<<NS * NFW, 256, smem>>>(X, W, (int*)d_out);
}

// round 3
// speedup vs baseline: 2.5501x; 1.0058x over previous
#include <cuda_runtime.h>

#define NS     8
#define NC     128
#define KT     32
#define KF     16
#define FREQ   256
#define NFW    15
#define THR    15.0f
#define LPRE   431

#define TCOLS       31
#define TILE_PAD    13364              // 431*31 = 13361, padded for alignment
#define WPITCH      65                 // 64 channels + 1 pad -> conflict-free transposed LDS/STS
#define WSM_FLOATS  (512 * WPITCH)     // 33280
#define SMEM_FLOATS (TILE_PAD + WSM_FLOATS)   // 46644 floats = 186,576 B

// pool bit per (section, fwin, channel)
__device__ int      g_pool[NS * NFW * NC];
__device__ unsigned g_done;            // zero at load; last CTA resets to 0 each run

__global__ __launch_bounds__(256, 1)
void conv_pool_winner_kernel(const float* __restrict__ X,
                             const float* __restrict__ W,
                             int* __restrict__ out)
{
    extern __shared__ float sm[];
    float* tile = sm;                  // [431][31] x window
    float* wsm  = sm + TILE_PAD;       // transposed weights [512][WPITCH]

    __shared__ unsigned s_fired[2];
    __shared__ int s_last, s_any, s_key;

    const int s    = blockIdx.x / NFW;
    const int fwin = blockIdx.x % NFW;
    const int tid  = threadIdx.x;
    const int lane = tid & 31;
    const int c    = tid & 63;         // channel within half
    const int j    = tid >> 6;         // probe slot 0..3 (uniform per warp)
    const int col0 = fwin * 16;
    const int sec  = s * 400;

    // ---- stage X window [sec..sec+431) x [col0..col0+31) ----
    for (int r = tid >> 5; r < LPRE; r += 8)
        if (lane < TCOLS)
            tile[r * TCOLS + lane] = X[(sec + r) * FREQ + col0 + lane];

    const float4* W4 = (const float4*)(W + (size_t)s * NC * KT * KF);

    for (int half = 0; half < 2; ++half) {
        const int cbase = half * 64;
        __syncthreads();                       // wsm reuse + fired reset barrier
        if (tid < 2) s_fired[tid] = 0u;

        // stage W transposed: wsm[kk*65 + cc] = W[s][cbase+cc][kk]
        for (int i = tid; i < 64 * 128; i += 256) {
            int cc = i >> 7, k4 = i & 127;
            float4 w = W4[(cbase + cc) * 128 + k4];
            int kk = k4 * 4;
            wsm[(kk + 0) * WPITCH + cc] = w.x;
            wsm[(kk + 1) * WPITCH + cc] = w.y;
            wsm[(kk + 2) * WPITCH + cc] = w.z;
            wsm[(kk + 3) * WPITCH + cc] = w.w;
        }
        __syncthreads();

        // ---- probe loop: full coverage of 6400 pots in decorrelated order ----
        for (int k = 0; k < 1600; ++k) {
            bool mine = ((s_fired[c >> 5] >> (c & 31)) & 1u) == 0u;
            if (__ballot_sync(0xffffffffu, mine)) {
                if (mine) {
                    int p   = k * 4 + j;              // 0..6399, each exactly once
                    int idx = (p * 2339) % 6400;      // gcd(2339,6400)=1
                    int t   = idx >> 4;               // 0..399
                    int f   = idx & 15;               // 0..15
                    const float* xr = tile + t * TCOLS + f;
                    const float* wr = wsm + c;
                    float a0 = 0.f, a1 = 0.f, a2 = 0.f, a3 = 0.f;
                    #pragma unroll 4
                    for (int kt = 0; kt < KT; ++kt) {
                        const float* xq = xr + kt * TCOLS;
                        const float* wq = wr + kt * KF * WPITCH;
                        #pragma unroll
                        for (int kf = 0; kf < KF; kf += 4) {
                            a0 = fmaf(xq[kf + 0], wq[(kf + 0) * WPITCH], a0);
                            a1 = fmaf(xq[kf + 1], wq[(kf + 1) * WPITCH], a1);
                            a2 = fmaf(xq[kf + 2], wq[(kf + 2) * WPITCH], a2);
                            a3 = fmaf(xq[kf + 3], wq[(kf + 3) * WPITCH], a3);
                        }
                    }
                    float pot = (a0 + a1) + (a2 + a3);
                    if (pot >= THR) atomicOr(&s_fired[c >> 5], 1u << (c & 31));
                }
            }
            __syncthreads();
            if ((s_fired[0] & s_fired[1]) == 0xffffffffu) break;
        }

        if (tid < 64)
            g_pool[(s * NFW + fwin) * NC + cbase + tid] =
                (int)((s_fired[tid >> 5] >> (tid & 31)) & 1u);
    }

    // ---- fused winner reduction: last CTA to finish does it ----
    __threadfence();
    if (tid == 0) {
        unsigned n = atomicAdd(&g_done, 1u);
        s_last = (n == gridDim.x - 1u);
    }
    __syncthreads();
    if (!s_last) return;
    __threadfence();

    unsigned char* mbuf = (unsigned char*)sm;   // reuse smem (post-sync)
    if (tid == 0) { s_any = 0; s_key = -1; }
    __syncthreads();

    int localany = 0;
    for (int cell = tid; cell < NC * NFW; cell += 256) {
        int cc = cell / NFW, f = cell % NFW;    // flat order c*15+f (matches jnp.argmax)
        unsigned mask = 0; int cnt = 0;
        #pragma unroll
        for (int ss = 0; ss < NS; ++ss) {
            int b = g_pool[(ss * NFW + f) * NC + cc];
            mask |= (unsigned)b << ss;
            cnt  += b;
        }
        int e = 8 - cnt; e = e < 0 ? 0 : (e > 7 ? 7 : e);
        int val = (int)((mask >> e) & 1u);
        mbuf[cell] = (unsigned char)((cnt << 1) | val);
        if (cnt > 0 && val > 0) localany = 1;
    }
    if (localany) atomicOr(&s_any, 1);
    __syncthreads();

    const int v = s_any * 8;
    for (int cell = tid; cell < NC * NFW; cell += 256) {
        int d = mbuf[cell];
        int total = (d >> 1) * ((d & 1) + v);
        int key = (total << 11) | (2047 - cell);   // first-occurrence argmax tie-break
        atomicMax(&s_key, key);
    }
    __syncthreads();

    if (tid == 0) {
        int key   = s_key;
        int total = key >> 11;
        int cell  = 2047 - (key & 2047);
        out[0] = total ? (cell / NFW) : -1;
        g_done = 0;                               // reset for next replay
    }
}

extern "C" void kernel_launch(void* const* d_in, const int* in_sizes, int n_in,
                              void* d_out, int out_size)
{
    (void)n_in; (void)out_size;
    const float* X = (const float*)d_in[0];
    const float* W = (const float*)d_in[1];
    if (in_sizes[0] == NS * NC * KT * KF) { const float* t = X; X = W; W = t; }

    const size_t smem = (size_t)SMEM_FLOATS * sizeof(float);   // 186,576 B
    cudaFuncSetAttribute(conv_pool_winner_kernel,
                         cudaFuncAttributeMaxDynamicSharedMemorySize, (int)smem);

    conv_pool_winner_kernel<<<NS * NFW, 256, smem>>>(X, W, (int*)d_out);
}

// round 5
// speedup vs baseline: 4.1796x; 1.6390x over previous
#include <cuda_runtime.h>

#define NS 8
#define NC 128
#define KT 32
#define KF 16
#define FREQ 256
#define NFW 15
#define THR 15.0f
#define LPRE 431
#define NPOT 6400
#define MARGIN 0.05f

#define TP 33
#define S_OFF    14224
#define SIDX_OFF 20624
#define W_OFF    23824
#define SMEM_F   56592   /* 226,368 bytes */

__device__ int      g_pool[NS * NFW * NC];
__device__ unsigned g_done;

__global__ __launch_bounds__(512, 1)
void spyke_kernel(const float* __restrict__ X, const float* __restrict__ W,
                  int* __restrict__ out)
{
    extern __shared__ float sm[];
    float*          tile = sm;
    float*          Sarr = sm + S_OFF;
    unsigned short* sidx = (unsigned short*)(sm + SIDX_OFF);
    float4*         w4   = (float4*)(sm + W_OFF);

    // prep overlays inside the (not yet written) weight region
    float* Rrow  = sm + W_OFF;
    float* Rrow2 = sm + W_OFF + 6896;
    int*   hist  = (int*)(sm + W_OFF + 13824);
    int*   bst   = (int*)(sm + W_OFF + 14100);

    __shared__ unsigned s_fired[2], s_zero[2];
    __shared__ int s_smin_i, s_smax_i, s_sig_i, s_last, s_any, s_key;
    __shared__ float s_smin, s_scale, s_inv, s_sigmax;
    __shared__ float sSw[64], s_req[64];

    const int s = blockIdx.x / NFW, fwin = blockIdx.x % NFW;
    const int tid = threadIdx.x, col0 = fwin * 16, sec = s * 400;

    if (tid == 0) { s_smin_i = 0x7f7fffff; s_smax_i = 0; s_sig_i = 0; }

    for (int i = tid; i < LPRE * 31; i += 512) {
        int r = i / 31, c = i - r * 31;
        tile[r * TP + c] = X[(sec + r) * FREQ + col0 + c];
    }
    __syncthreads();

    // row sliding sums + sumsq over kf-window of 16
    if (tid < LPRE) {
        float a = 0.f, a2 = 0.f;
        for (int c = 0; c < 16; ++c) { float x = tile[tid*TP + c]; a += x; a2 += x*x; }
        Rrow[tid*16] = a; Rrow2[tid*16] = a2;
        for (int f = 1; f < 16; ++f) {
            float xo = tile[tid*TP + f - 1], xn = tile[tid*TP + f + 15];
            a += xn - xo; a2 += xn*xn - xo*xo;
            Rrow[tid*16 + f] = a; Rrow2[tid*16 + f] = a2;
        }
    }
    if (tid >= 160 && tid < 416) hist[tid - 160] = 0;
    __syncthreads();

    // column sliding over kt-window of 32: S(t,f); track min/max/sigmax
    if (tid < 160) {
        int f = tid / 10, t0 = (tid % 10) * 40;
        float a = 0.f, a2 = 0.f;
        for (int k = 0; k < 32; ++k) { a += Rrow[(t0+k)*16+f]; a2 += Rrow2[(t0+k)*16+f]; }
        float lmin = 1e30f, lmax = -1e30f, lsig = 0.f;
        for (int t = t0; t < t0 + 40; ++t) {
            Sarr[t*16 + f] = a;
            lsig = fmaxf(lsig, a2 - a*a*(1.0f/512.0f));
            lmin = fminf(lmin, a); lmax = fmaxf(lmax, a);
            if (t <= 398) {
                a  += Rrow[(t+32)*16+f]  - Rrow[t*16+f];
                a2 += Rrow2[(t+32)*16+f] - Rrow2[t*16+f];
            }
        }
        atomicMin(&s_smin_i, __float_as_int(lmin));
        atomicMax(&s_smax_i, __float_as_int(lmax));
        atomicMax(&s_sig_i,  __float_as_int(fmaxf(lsig, 0.f)));
    }
    __syncthreads();
    if (tid == 0) {
        float smin = __int_as_float(s_smin_i), smax = __int_as_float(s_smax_i);
        float inv = fmaxf(smax - smin, 1e-9f) * (1.0f/255.0f);
        s_smin = smin; s_inv = inv; s_scale = 1.0f / inv;
        s_sigmax = sqrtf(__int_as_float(s_sig_i));
    }
    __syncthreads();

    // bucket-sort positions by S, descending
    for (int p = tid; p < NPOT; p += 512) {
        int b = (int)((Sarr[p] - s_smin) * s_scale);
        b = b < 0 ? 0 : (b > 255 ? 255 : b);
        atomicAdd(&hist[255 - b], 1);
    }
    __syncthreads();
    if (tid < 32) {
        int loc[8], ssum = 0;
        #pragma unroll
        for (int k = 0; k < 8; ++k) { loc[k] = ssum; ssum += hist[tid*8 + k]; }
        int excl = ssum;
        for (int d = 1; d < 32; d <<= 1) {
            int v = __shfl_up_sync(0xffffffffu, excl, d);
            if ((int)tid >= d) excl += v;
        }
        excl -= ssum;
        #pragma unroll
        for (int k = 0; k < 8; ++k) bst[tid*8 + k] = excl + loc[k];
    }
    __syncthreads();
    if (tid < 256) hist[tid] = bst[tid];
    __syncthreads();
    for (int p = tid; p < NPOT; p += 512) {
        int b = (int)((Sarr[p] - s_smin) * s_scale);
        b = b < 0 ? 0 : (b > 255 ? 255 : b);
        sidx[atomicAdd(&hist[255 - b], 1)] = (unsigned short)p;
    }

    const float4* Wg = (const float4*)(W + (size_t)s * NC * KT * KF);
    const int cc8 = tid >> 3, q8 = tid & 7;

    for (int half = 0; half < 2; ++half) {
        __syncthreads();
        if (tid < 2) { s_fired[tid] = 0u; s_zero[tid] = 0u; }

        // stage W swizzled; accumulate Sw and ||w||^2
        float wsum = 0.f, wsq = 0.f;
        #pragma unroll
        for (int k = 0; k < 16; ++k) {
            int q = q8 + k*8;
            float4 v = Wg[(half*64 + cc8)*128 + q];
            w4[cc8*128 + (q ^ (cc8 & 7))] = v;
            wsum += (v.x + v.y) + (v.z + v.w);
            wsq  += (v.x*v.x + v.y*v.y) + (v.z*v.z + v.w*v.w);
        }
        #pragma unroll
        for (int d = 4; d; d >>= 1) {
            wsum += __shfl_down_sync(0xffffffffu, wsum, d);
            wsq  += __shfl_down_sync(0xffffffffu, wsq,  d);
        }
        if (q8 == 0) { sSw[cc8] = wsum; s_req[cc8] = wsq; }
        __syncthreads();
        if (tid < 64) {
            float Sw = sSw[tid];
            float B  = sqrtf(fmaxf(s_req[tid] - Sw*Sw*(1.0f/512.0f), 0.f));
            s_req[tid] = (Sw > 1.0f) ? (THR - MARGIN - B*s_sigmax) * (512.0f / Sw) : -1e30f;
        }
        __syncthreads();

        const int c = tid & 63, j = tid >> 6, cw = c >> 5, cx = c & 7;
        const unsigned cb = 1u << (c & 31);
        const float4* wrow = w4 + c * 128;

        int rank0 = 0;
        while (rank0 < NPOT) {
            unsigned done = (s_fired[0] | s_zero[0]) & (s_fired[1] | s_zero[1]);
            if (done == 0xffffffffu) break;
            int nsl = rank0 < 4 ? 2 : (rank0 < 8 ? 4 : 8);
            if (j < nsl) {
                bool mine = (((s_fired[cw] | s_zero[cw]) >> (c & 31)) & 1u) == 0u;
                int rank = rank0 + j;
                if (__ballot_sync(0xffffffffu, mine) && rank < NPOT) {
                    if (mine) {
                        int p = sidx[rank], t = p >> 4, f = p & 15;
                        const float* xb = tile + t * TP + f;
                        float a0=0.f, a1=0.f, a2=0.f, a3=0.f;
                        #pragma unroll 4
                        for (int kt = 0; kt < KT; ++kt) {
                            const float* xr = xb + kt * TP;
                            #pragma unroll
                            for (int g = 0; g < 4; ++g) {
                                float4 w = wrow[(kt*4 + g) ^ cx];
                                a0 = fmaf(xr[4*g+0], w.x, a0);
                                a1 = fmaf(xr[4*g+1], w.y, a1);
                                a2 = fmaf(xr[4*g+2], w.z, a2);
                                a3 = fmaf(xr[4*g+3], w.w, a3);
                            }
                        }
                        float pot = (a0 + a1) + (a2 + a3);
                        if (pot >= THR) atomicOr(&s_fired[cw], cb);
                        else {
                            int b = (int)((Sarr[p] - s_smin) * s_scale);
                            float hi = s_smin + (float)(b + 1) * s_inv;
                            if (hi < s_req[c]) atomicOr(&s_zero[cw], cb);
                        }
                    }
                }
            }
            rank0 += nsl;
            __syncthreads();
        }
        if (tid < 64)
            g_pool[(s * NFW + fwin) * NC + half*64 + tid] =
                (int)((s_fired[tid >> 5] >> (tid & 31)) & 1u);
    }

    // fused winner reduction (last CTA)
    __threadfence();
    if (tid == 0) s_last = (atomicAdd(&g_done, 1u) == gridDim.x - 1u);
    __syncthreads();
    if (!s_last) return;
    __threadfence();

    unsigned char* mbuf = (unsigned char*)sm;
    if (tid == 0) { s_any = 0; s_key = -1; }
    __syncthreads();

    int localany = 0;
    for (int cell = tid; cell < NC * NFW; cell += 512) {
        int cc = cell / NFW, f = cell % NFW;
        unsigned mask = 0; int cnt = 0;
        #pragma unroll
        for (int ss = 0; ss < NS; ++ss) {
            int b = g_pool[(ss * NFW + f) * NC + cc];
            mask |= (unsigned)b << ss; cnt += b;
        }
        int e = 8 - cnt; e = e < 0 ? 0 : (e > 7 ? 7 : e);
        int val = (int)((mask >> e) & 1u);
        mbuf[cell] = (unsigned char)((cnt << 1) | val);
        if (cnt > 0 && val > 0) localany = 1;
    }
    if (localany) atomicOr(&s_any, 1);
    __syncthreads();

    const int v = s_any * 8;
    for (int cell = tid; cell < NC * NFW; cell += 512) {
        int d = mbuf[cell];
        int total = (d >> 1) * ((d & 1) + v);
        atomicMax(&s_key, (total << 11) | (2047 - cell));
    }
    __syncthreads();

    if (tid == 0) {
        int key = s_key, total = key >> 11, cell = 2047 - (key & 2047);
        out[0] = total ? (cell / NFW) : -1;
        g_done = 0;
    }
}

extern "C" void kernel_launch(void* const* d_in, const int* in_sizes, int n_in,
                              void* d_out, int out_size)
{
    (void)n_in; (void)out_size;
    const float* X = (const float*)d_in[0];
    const float* W = (const float*)d_in[1];
    if (in_sizes[0] == NS * NC * KT * KF) { const float* t = X; X = W; W = t; }

    const size_t smem = (size_t)SMEM_F * sizeof(float);
    cudaFuncSetAttribute(spyke_kernel,
                         cudaFuncAttributeMaxDynamicSharedMemorySize, (int)smem);
    spyke_kernel<<<NS * NFW, 512, smem>>>(X, W, (int*)d_out);
}